// round 14
// baseline (speedup 1.0000x reference)
#include <cuda_runtime.h>
#include <cuda_bf16.h>
#include <cuda_fp16.h>
#include <cstdint>

#define BSZ 16
#define L 1024
#define HDIM 768
#define OUTW (4*HDIM)

typedef __nv_bfloat16 bf16;

// ---------------- scratch (device globals; allocation-free rule) ------------
__device__ __align__(256) bf16 g_x1h[(size_t)BSZ*L*HDIM];
__device__ __align__(256) bf16 g_x1l[(size_t)BSZ*L*HDIM];
__device__ __align__(256) bf16 g_x2h[(size_t)BSZ*L*HDIM];   // gathered x2 rows hi (bf16)
__device__ __align__(256) bf16 g_x2l[(size_t)BSZ*L*HDIM];   // gathered x2 rows lo (bf16)
__device__ __align__(256) bf16 g_Wh [(size_t)HDIM*HDIM];
__device__ __align__(256) bf16 g_Wl [(size_t)HDIM*HDIM];
__device__ __align__(256) __half g_xph[(size_t)BSZ*L*HDIM]; // xproj hi (fp16)
__device__ __align__(256) __half g_xpl[(size_t)BSZ*L*HDIM]; // xproj lo (fp16)
__device__ __align__(256) __half g_yph[(size_t)BSZ*L*HDIM]; // yproj hi only (fp16)
__device__ __align__(256) __half g_x2Th[(size_t)BSZ*HDIM*L]; // gathered transpose (fp16)
__device__ __align__(256) __half g_ah [(size_t)BSZ*L*L];     // alpha (compacted cols)
__device__ float g_scores[(size_t)BSZ*L*L];
__device__ int g_cnt[BSZ];
__device__ int g_idx[BSZ][L];

// ---------------- helpers ---------------------------------------------------
__device__ __forceinline__ uint32_t smem_u32(const void* p) {
    uint32_t a;
    asm("{ .reg .u64 t; cvta.to.shared.u64 t, %1; cvt.u32.u64 %0, t; }"
        : "=r"(a) : "l"(p));
    return a;
}
__device__ __forceinline__ void cp16(uint32_t dst, const void* src) {
    asm volatile("cp.async.cg.shared.global [%0], [%1], 16;"
                 :: "r"(dst), "l"(src) : "memory");
}
__device__ __forceinline__ void ldmx4(uint32_t (&r)[4], uint32_t addr) {
    asm volatile("ldmatrix.sync.aligned.m8n8.x4.shared.b16 {%0,%1,%2,%3}, [%4];"
                 : "=r"(r[0]), "=r"(r[1]), "=r"(r[2]), "=r"(r[3]) : "r"(addr));
}
__device__ __forceinline__ void mma16816(float (&c)[4], const uint32_t (&a)[4],
                                         uint32_t b0, uint32_t b1) {
    asm volatile(
        "mma.sync.aligned.m16n8k16.row.col.f32.bf16.bf16.f32 "
        "{%0,%1,%2,%3}, {%4,%5,%6,%7}, {%8,%9}, {%0,%1,%2,%3};"
        : "+f"(c[0]), "+f"(c[1]), "+f"(c[2]), "+f"(c[3])
        : "r"(a[0]), "r"(a[1]), "r"(a[2]), "r"(a[3]), "r"(b0), "r"(b1));
}
__device__ __forceinline__ void mma16816_f16(float (&c)[4], const uint32_t (&a)[4],
                                             uint32_t b0, uint32_t b1) {
    asm volatile(
        "mma.sync.aligned.m16n8k16.row.col.f32.f16.f16.f32 "
        "{%0,%1,%2,%3}, {%4,%5,%6,%7}, {%8,%9}, {%0,%1,%2,%3};"
        : "+f"(c[0]), "+f"(c[1]), "+f"(c[2]), "+f"(c[3])
        : "r"(a[0]), "r"(a[1]), "r"(a[2]), "r"(a[3]), "r"(b0), "r"(b1));
}
__device__ __forceinline__ uint32_t pack_bf(bf16 a, bf16 b) {
    uint16_t ua = *(uint16_t*)&a, ub = *(uint16_t*)&b;
    return (uint32_t)ua | ((uint32_t)ub << 16);
}
__device__ __forceinline__ uint32_t pack_h(__half a, __half b) {
    uint16_t ua = *(uint16_t*)&a, ub = *(uint16_t*)&b;
    return (uint32_t)ua | ((uint32_t)ub << 16);
}
__device__ __forceinline__ void split1(float f, bf16& h, bf16& l) {
    h = __float2bfloat16(f);
    l = __float2bfloat16(f - __bfloat162float(h));
}
__device__ __forceinline__ void split1h(float f, __half& h, __half& l) {
    h = __float2half(f);
    l = __float2half(f - __half2float(h));
}

#define ROWB 80
#define TILEB (128 * ROWB)
#define STAGEB (4 * TILEB)
#define SMEMB (2 * STAGEB)          // 3-pass bf16: 81920
#define STAGEB2 (3 * TILEB)
#define SMEMB2 (2 * STAGEB2)        // 2-pass fp16: 61440
#define STAGEB1 (2 * TILEB)
#define SMEMB1 (2 * STAGEB1)        // 1-pass fp16: 40960 (static)

// ---------------------------------------------------------------------------
// 3-pass split-bf16 mainloop: acc += Ah.Bh^T + Ah.Bl^T + Al.Bh^T
// ---------------------------------------------------------------------------
__device__ __forceinline__ void gemm_core(
    const bf16* __restrict__ Ah, const bf16* __restrict__ Al, int lda,
    const bf16* __restrict__ Bh, const bf16* __restrict__ Bl, int ldb,
    int K, char* smem, float (&acc)[4][4][4])
{
    const int tid  = threadIdx.x;
    const int lane = tid & 31;
    const int wid  = tid >> 5;
    const int wm   = (wid & 1) * 64;
    const int wn   = (wid >> 1) * 32;
    const uint32_t sbase = smem_u32(smem);
    const int nk = K >> 5;

    const int ra = tid >> 2, ca = tid & 3;
    const int rb = ra + 64;

    for (int i = -1; i < nk; ++i) {
        if (i + 1 < nk) {
            const int kt = (i + 1) << 5;
            const uint32_t st = sbase + ((i + 1) & 1) * STAGEB;
            const uint32_t o0 = ra * ROWB + ca * 16;
            const uint32_t o1 = rb * ROWB + ca * 16;
            cp16(st + o0,             Ah + (size_t)ra * lda + kt + ca * 8);
            cp16(st + o1,             Ah + (size_t)rb * lda + kt + ca * 8);
            cp16(st + TILEB + o0,     Al + (size_t)ra * lda + kt + ca * 8);
            cp16(st + TILEB + o1,     Al + (size_t)rb * lda + kt + ca * 8);
            cp16(st + 2*TILEB + o0,   Bh + (size_t)ra * ldb + kt + ca * 8);
            cp16(st + 2*TILEB + o1,   Bh + (size_t)rb * ldb + kt + ca * 8);
            cp16(st + 3*TILEB + o0,   Bl + (size_t)ra * ldb + kt + ca * 8);
            cp16(st + 3*TILEB + o1,   Bl + (size_t)rb * ldb + kt + ca * 8);
            asm volatile("cp.async.commit_group;" ::: "memory");
        }
        if (i < 0) continue;
        if (i + 1 < nk)
            asm volatile("cp.async.wait_group 1;" ::: "memory");
        else
            asm volatile("cp.async.wait_group 0;" ::: "memory");
        __syncthreads();

        const uint32_t sAh = sbase + (i & 1) * STAGEB;
        const uint32_t sAl = sAh + TILEB;
        const uint32_t sBh = sAh + 2 * TILEB;
        const uint32_t sBl = sAh + 3 * TILEB;
        #pragma unroll
        for (int kh = 0; kh < 2; ++kh) {
            const uint32_t coff = (uint32_t)(kh * 2 + (lane >> 4)) * 16;
            const uint32_t brow = (uint32_t)(wn + (lane & 15)) * ROWB + coff;
            uint32_t bh0[4], bh1[4], bl0[4], bl1[4];
            ldmx4(bh0, sBh + brow);
            ldmx4(bh1, sBh + brow + 16u * ROWB);
            ldmx4(bl0, sBl + brow);
            ldmx4(bl1, sBl + brow + 16u * ROWB);
            #pragma unroll
            for (int mi = 0; mi < 4; ++mi) {
                const uint32_t arow = (uint32_t)(wm + mi * 16 + (lane & 15)) * ROWB + coff;
                uint32_t ah[4], al[4];
                ldmx4(ah, sAh + arow);
                ldmx4(al, sAl + arow);
                mma16816(acc[mi][0], ah, bh0[0], bh0[2]);
                mma16816(acc[mi][1], ah, bh0[1], bh0[3]);
                mma16816(acc[mi][2], ah, bh1[0], bh1[2]);
                mma16816(acc[mi][3], ah, bh1[1], bh1[3]);
                mma16816(acc[mi][0], ah, bl0[0], bl0[2]);
                mma16816(acc[mi][1], ah, bl0[1], bl0[3]);
                mma16816(acc[mi][2], ah, bl1[0], bl1[2]);
                mma16816(acc[mi][3], ah, bl1[1], bl1[3]);
                mma16816(acc[mi][0], al, bh0[0], bh0[2]);
                mma16816(acc[mi][1], al, bh0[1], bh0[3]);
                mma16816(acc[mi][2], al, bh1[0], bh1[2]);
                mma16816(acc[mi][3], al, bh1[1], bh1[3]);
            }
        }
        __syncthreads();
    }
}

// ---------------------------------------------------------------------------
// 2-pass fp16 mainloop: acc += (Ah + Al).Bh^T
// ---------------------------------------------------------------------------
__device__ __forceinline__ void gemm_core_2p(
    const __half* __restrict__ Ah, const __half* __restrict__ Al, int lda,
    const __half* __restrict__ Bh, int ldb,
    int K, char* smem, float (&acc)[4][4][4])
{
    const int tid  = threadIdx.x;
    const int lane = tid & 31;
    const int wid  = tid >> 5;
    const int wm   = (wid & 1) * 64;
    const int wn   = (wid >> 1) * 32;
    const uint32_t sbase = smem_u32(smem);
    const int nk = K >> 5;

    const int ra = tid >> 2, ca = tid & 3;
    const int rb = ra + 64;

    for (int i = -1; i < nk; ++i) {
        if (i + 1 < nk) {
            const int kt = (i + 1) << 5;
            const uint32_t st = sbase + ((i + 1) & 1) * STAGEB2;
            const uint32_t o0 = ra * ROWB + ca * 16;
            const uint32_t o1 = rb * ROWB + ca * 16;
            cp16(st + o0,           Ah + (size_t)ra * lda + kt + ca * 8);
            cp16(st + o1,           Ah + (size_t)rb * lda + kt + ca * 8);
            cp16(st + TILEB + o0,   Al + (size_t)ra * lda + kt + ca * 8);
            cp16(st + TILEB + o1,   Al + (size_t)rb * lda + kt + ca * 8);
            cp16(st + 2*TILEB + o0, Bh + (size_t)ra * ldb + kt + ca * 8);
            cp16(st + 2*TILEB + o1, Bh + (size_t)rb * ldb + kt + ca * 8);
            asm volatile("cp.async.commit_group;" ::: "memory");
        }
        if (i < 0) continue;
        if (i + 1 < nk)
            asm volatile("cp.async.wait_group 1;" ::: "memory");
        else
            asm volatile("cp.async.wait_group 0;" ::: "memory");
        __syncthreads();

        const uint32_t sAh = sbase + (i & 1) * STAGEB2;
        const uint32_t sAl = sAh + TILEB;
        const uint32_t sBh = sAh + 2 * TILEB;
        #pragma unroll
        for (int kh = 0; kh < 2; ++kh) {
            const uint32_t coff = (uint32_t)(kh * 2 + (lane >> 4)) * 16;
            const uint32_t brow = (uint32_t)(wn + (lane & 15)) * ROWB + coff;
            uint32_t bh0[4], bh1[4];
            ldmx4(bh0, sBh + brow);
            ldmx4(bh1, sBh + brow + 16u * ROWB);
            #pragma unroll
            for (int mi = 0; mi < 4; ++mi) {
                const uint32_t arow = (uint32_t)(wm + mi * 16 + (lane & 15)) * ROWB + coff;
                uint32_t ah[4], al[4];
                ldmx4(ah, sAh + arow);
                ldmx4(al, sAl + arow);
                mma16816_f16(acc[mi][0], ah, bh0[0], bh0[2]);
                mma16816_f16(acc[mi][1], ah, bh0[1], bh0[3]);
                mma16816_f16(acc[mi][2], ah, bh1[0], bh1[2]);
                mma16816_f16(acc[mi][3], ah, bh1[1], bh1[3]);
                mma16816_f16(acc[mi][0], al, bh0[0], bh0[2]);
                mma16816_f16(acc[mi][1], al, bh0[1], bh0[3]);
                mma16816_f16(acc[mi][2], al, bh1[0], bh1[2]);
                mma16816_f16(acc[mi][3], al, bh1[1], bh1[3]);
            }
        }
        __syncthreads();
    }
}

// ---------------------------------------------------------------------------
// 1-pass fp16 mainloop: acc += A.B^T
// ---------------------------------------------------------------------------
__device__ __forceinline__ void gemm_core_1p(
    const __half* __restrict__ A, int lda,
    const __half* __restrict__ B, int ldb,
    int K, char* smem, float (&acc)[4][4][4])
{
    const int tid  = threadIdx.x;
    const int lane = tid & 31;
    const int wid  = tid >> 5;
    const int wm   = (wid & 1) * 64;
    const int wn   = (wid >> 1) * 32;
    const uint32_t sbase = smem_u32(smem);
    const int nk = K >> 5;

    const int ra = tid >> 2, ca = tid & 3;
    const int rb = ra + 64;

    for (int i = -1; i < nk; ++i) {
        if (i + 1 < nk) {
            const int kt = (i + 1) << 5;
            const uint32_t st = sbase + ((i + 1) & 1) * STAGEB1;
            const uint32_t o0 = ra * ROWB + ca * 16;
            const uint32_t o1 = rb * ROWB + ca * 16;
            cp16(st + o0,         A + (size_t)ra * lda + kt + ca * 8);
            cp16(st + o1,         A + (size_t)rb * lda + kt + ca * 8);
            cp16(st + TILEB + o0, B + (size_t)ra * ldb + kt + ca * 8);
            cp16(st + TILEB + o1, B + (size_t)rb * ldb + kt + ca * 8);
            asm volatile("cp.async.commit_group;" ::: "memory");
        }
        if (i < 0) continue;
        if (i + 1 < nk)
            asm volatile("cp.async.wait_group 1;" ::: "memory");
        else
            asm volatile("cp.async.wait_group 0;" ::: "memory");
        __syncthreads();

        const uint32_t sA = sbase + (i & 1) * STAGEB1;
        const uint32_t sB = sA + TILEB;
        #pragma unroll
        for (int kh = 0; kh < 2; ++kh) {
            const uint32_t coff = (uint32_t)(kh * 2 + (lane >> 4)) * 16;
            const uint32_t brow = (uint32_t)(wn + (lane & 15)) * ROWB + coff;
            uint32_t bb0[4], bb1[4];
            ldmx4(bb0, sB + brow);
            ldmx4(bb1, sB + brow + 16u * ROWB);
            #pragma unroll
            for (int mi = 0; mi < 4; ++mi) {
                uint32_t aa[4];
                ldmx4(aa, sA + (uint32_t)(wm + mi * 16 + (lane & 15)) * ROWB + coff);
                mma16816_f16(acc[mi][0], aa, bb0[0], bb0[2]);
                mma16816_f16(acc[mi][1], aa, bb0[1], bb0[3]);
                mma16816_f16(acc[mi][2], aa, bb1[0], bb1[2]);
                mma16816_f16(acc[mi][3], aa, bb1[1], bb1[3]);
            }
        }
        __syncthreads();
    }
}

// ---------------------------------------------------------------------------
// Index build: per-batch compacted list of unmasked columns (block scan)
// ---------------------------------------------------------------------------
__global__ __launch_bounds__(256) void index_kernel(const int* __restrict__ x2_mask)
{
    const int b = blockIdx.x, tid = threadIdx.x;
    __shared__ int wsum[8];
    const int* m = x2_mask + (size_t)b * L;
    const int base = tid * 4;
    int keep[4], cnt = 0;
    #pragma unroll
    for (int j = 0; j < 4; ++j) { keep[j] = (m[base + j] == 0); cnt += keep[j]; }
    const int lane = tid & 31, w = tid >> 5;
    int v = cnt;
    #pragma unroll
    for (int o = 1; o < 32; o <<= 1) {
        int t = __shfl_up_sync(0xffffffffu, v, o);
        if (lane >= o) v += t;
    }
    if (lane == 31) wsum[w] = v;
    __syncthreads();
    int woff = 0;
    for (int i = 0; i < w; ++i) woff += wsum[i];
    int pos = woff + v - cnt;   // exclusive prefix
    #pragma unroll
    for (int j = 0; j < 4; ++j)
        if (keep[j]) g_idx[b][pos++] = base + j;
    if (tid == 255) g_cnt[b] = woff + v;
}

// ---------------------------------------------------------------------------
// Merged split (x1 then W), one launch
// ---------------------------------------------------------------------------
#define N4X (BSZ*L*HDIM/4)
#define N4W (HDIM*HDIM/4)
__global__ __launch_bounds__(256) void split_kernel(const float* __restrict__ x1,
                                                    const float* __restrict__ W)
{
    int i = blockIdx.x * 256 + threadIdx.x;
    const float* in;
    bf16 *hi, *lo;
    int j;
    if (i < N4X)      { in = x1; hi = g_x1h; lo = g_x1l; j = i; }
    else if (i < N4X + N4W) { in = W; hi = g_Wh; lo = g_Wl; j = i - N4X; }
    else return;
    float4 v = ((const float4*)in)[j];
    bf16 h0, h1, h2, h3, l0, l1, l2, l3;
    split1(v.x, h0, l0); split1(v.y, h1, l1);
    split1(v.z, h2, l2); split1(v.w, h3, l3);
    ((uint2*)hi)[j] = make_uint2(pack_bf(h0, h1), pack_bf(h2, h3));
    ((uint2*)lo)[j] = make_uint2(pack_bf(l0, l1), pack_bf(l2, l3));
}

// ---------------------------------------------------------------------------
// prep_x2: one x2 read -> compacted rows bf16 hi/lo + fp16 transpose
// ---------------------------------------------------------------------------
__global__ __launch_bounds__(256) void prep_x2(const float* __restrict__ x2)
{
    __shared__ float t[32][33];
    const int b = blockIdx.z;
    const int c = g_cnt[b];
    const int cpad = (c + 127) & ~127;
    const int h0 = blockIdx.x * 32, l0 = blockIdx.y * 32;
    if (l0 >= cpad) return;
    const int tx = threadIdx.x & 31, ty = threadIdx.x >> 5;
    #pragma unroll
    for (int j = 0; j < 4; ++j) {
        const int li = ty + j * 8;
        const int lg = l0 + li;
        float v = 0.f;
        if (lg < c) v = x2[((size_t)b * L + g_idx[b][lg]) * HDIM + h0 + tx];
        t[li][tx] = v;
        bf16 h, l; split1(v, h, l);
        const size_t o = ((size_t)b * L + lg) * HDIM + h0 + tx;
        g_x2h[o] = h;
        g_x2l[o] = l;
    }
    __syncthreads();
    #pragma unroll
    for (int j = 0; j < 4; ++j) {
        const int r = ty + j * 8;   // h-local
        g_x2Th[((size_t)b * HDIM + h0 + r) * L + l0 + tx] = __float2half(t[tx][r]);
    }
}

// ---------------------------------------------------------------------------
// Merged projection: grid (6, 256).
//   y < 128 : xproj tile (m0 = y*128 over BSZ*L rows) -> fp16 hi/lo
//   y >= 128: yproj tile (b = (y-128)/8, mt = (y-128)%8) -> fp16 hi, early-exit
// ---------------------------------------------------------------------------
__global__ __launch_bounds__(256, 2) void gemm_proj_xy(const float* __restrict__ bias)
{
    extern __shared__ __align__(128) char gsm[];
    const int yb = blockIdx.y;
    const int n0 = blockIdx.x * 128;
    const int tid = threadIdx.x, lane = tid & 31, wid = tid >> 5;
    const int wm = (wid & 1) * 64, wn = (wid >> 1) * 32;

    if (yb < 128) {
        const size_t m0 = (size_t)yb * 128;
        float acc[4][4][4] = {};
        gemm_core(g_x1h + m0 * HDIM, g_x1l + m0 * HDIM, HDIM,
                  g_Wh + (size_t)n0 * HDIM, g_Wl + (size_t)n0 * HDIM, HDIM,
                  HDIM, gsm, acc);
        #pragma unroll
        for (int mi = 0; mi < 4; ++mi)
            #pragma unroll
            for (int ni = 0; ni < 4; ++ni)
                #pragma unroll
                for (int h = 0; h < 2; ++h) {
                    const size_t m = m0 + wm + mi * 16 + (lane >> 2) + h * 8;
                    const int n = n0 + wn + ni * 8 + (lane & 3) * 2;
                    float f0 = fmaxf(acc[mi][ni][h * 2]     + bias[n],     0.f);
                    float f1 = fmaxf(acc[mi][ni][h * 2 + 1] + bias[n + 1], 0.f);
                    __half h0, l0, h1, l1;
                    split1h(f0, h0, l0); split1h(f1, h1, l1);
                    *(uint32_t*)(g_xph + m * HDIM + n) = pack_h(h0, h1);
                    *(uint32_t*)(g_xpl + m * HDIM + n) = pack_h(l0, l1);
                }
    } else {
        const int tindex = yb - 128;
        const int b = tindex >> 3;
        const size_t m0 = (size_t)(tindex & 7) * 128;
        const int cpad = (g_cnt[b] + 127) & ~127;
        if ((int)m0 >= cpad) return;
        const size_t boff = (size_t)b * L * HDIM;

        float acc[4][4][4] = {};
        gemm_core(g_x2h + boff + m0 * HDIM, g_x2l + boff + m0 * HDIM, HDIM,
                  g_Wh + (size_t)n0 * HDIM, g_Wl + (size_t)n0 * HDIM, HDIM,
                  HDIM, gsm, acc);
        #pragma unroll
        for (int mi = 0; mi < 4; ++mi)
            #pragma unroll
            for (int ni = 0; ni < 4; ++ni)
                #pragma unroll
                for (int h = 0; h < 2; ++h) {
                    const size_t m = m0 + wm + mi * 16 + (lane >> 2) + h * 8;
                    const int n = n0 + wn + ni * 8 + (lane & 3) * 2;
                    float f0 = fmaxf(acc[mi][ni][h * 2]     + bias[n],     0.f);
                    float f1 = fmaxf(acc[mi][ni][h * 2 + 1] + bias[n + 1], 0.f);
                    *(uint32_t*)(g_yph + boff + m * HDIM + n) =
                        pack_h(__float2half(f0), __float2half(f1));
                }
    }
}

// ---------------------------------------------------------------------------
// GEMM 2: scores = (xh+xl) . yh^T (2-pass fp16), -inf beyond count. grid (8,8,16)
// ---------------------------------------------------------------------------
__global__ __launch_bounds__(256, 2) void gemm_scores()
{
    extern __shared__ __align__(128) char gsm[];
    const int b = blockIdx.z;
    const int c = g_cnt[b];
    const int cpad = (c + 127) & ~127;
    const int n0 = blockIdx.x * 128;
    if (n0 >= cpad) return;

    float acc[4][4][4] = {};
    const size_t m0 = (size_t)blockIdx.y * 128;
    const size_t boff = (size_t)b * L * HDIM;

    gemm_core_2p(g_xph + boff + m0 * HDIM, g_xpl + boff + m0 * HDIM, HDIM,
                 g_yph + boff + (size_t)n0 * HDIM, HDIM,
                 HDIM, gsm, acc);

    const int tid = threadIdx.x, lane = tid & 31, wid = tid >> 5;
    const int wm = (wid & 1) * 64, wn = (wid >> 1) * 32;
    const float NEGINF = __int_as_float(0xff800000u);
    #pragma unroll
    for (int mi = 0; mi < 4; ++mi)
        #pragma unroll
        for (int ni = 0; ni < 4; ++ni)
            #pragma unroll
            for (int h = 0; h < 2; ++h) {
                const size_t m = m0 + wm + mi * 16 + (lane >> 2) + h * 8;
                const int n = n0 + wn + ni * 8 + (lane & 3) * 2;
                float2 o;
                o.x = (n     >= c) ? NEGINF : acc[mi][ni][h * 2];
                o.y = (n + 1 >= c) ? NEGINF : acc[mi][ni][h * 2 + 1];
                *(float2*)(g_scores + ((size_t)b * L + m) * L + n) = o;
            }
}

// ---------------------------------------------------------------------------
// Softmax over compacted cols; fp16 alpha out. grid(16384), 256 threads.
// ---------------------------------------------------------------------------
__global__ __launch_bounds__(256) void softmax_kernel()
{
    const int tid = threadIdx.x;
    const size_t row = blockIdx.x;
    const int b = (int)(row >> 10);
    const int cpad = (g_cnt[b] + 127) & ~127;
    const int col = tid * 4;
    const float NEGINF = __int_as_float(0xff800000u);

    float4 v = make_float4(NEGINF, NEGINF, NEGINF, NEGINF);
    if (col < cpad)
        v = *(((const float4*)g_scores) + row * (L / 4) + tid);

    __shared__ float smax[8];
    __shared__ float ssum[8];

    float m = fmaxf(fmaxf(v.x, v.y), fmaxf(v.z, v.w));
    #pragma unroll
    for (int o = 16; o > 0; o >>= 1)
        m = fmaxf(m, __shfl_xor_sync(0xffffffffu, m, o));
    if ((tid & 31) == 0) smax[tid >> 5] = m;
    __syncthreads();
    m = smax[0];
    #pragma unroll
    for (int w = 1; w < 8; ++w) m = fmaxf(m, smax[w]);

    float4 e;
    e.x = expf(v.x - m); e.y = expf(v.y - m);
    e.z = expf(v.z - m); e.w = expf(v.w - m);
    float s = (e.x + e.y) + (e.z + e.w);
    #pragma unroll
    for (int o = 16; o > 0; o >>= 1)
        s += __shfl_xor_sync(0xffffffffu, s, o);
    if ((tid & 31) == 0) ssum[tid >> 5] = s;
    __syncthreads();
    s = 0.f;
    #pragma unroll
    for (int w = 0; w < 8; ++w) s += ssum[w];

    const float inv = 1.0f / s;
    if (col < cpad) {
        e.x *= inv; e.y *= inv; e.z *= inv; e.w *= inv;
        *(uint2*)(g_ah + row * L + col) = make_uint2(
            pack_h(__float2half(e.x), __float2half(e.y)),
            pack_h(__float2half(e.z), __float2half(e.w)));
    }
}

// ---------------------------------------------------------------------------
// GEMM 3: att = alpha @ x2 over compacted K + concat epilogue. grid (6, 8, 16)
// ---------------------------------------------------------------------------
__global__ __launch_bounds__(256, 2) void gemm_att(const float* __restrict__ x1,
                                                   float* __restrict__ out)
{
    __shared__ __align__(128) char gsm[SMEMB1];
    float acc[4][4][4] = {};

    const int b = blockIdx.z;
    const int cpad = (g_cnt[b] + 127) & ~127;
    const size_t m0 = (size_t)blockIdx.y * 128;
    const int n0 = blockIdx.x * 128;

    gemm_core_1p(g_ah + ((size_t)b * L + m0) * L, L,
                 g_x2Th + ((size_t)b * HDIM + n0) * L, L,
                 cpad, gsm, acc);

    const int tid = threadIdx.x, lane = tid & 31, wid = tid >> 5;
    const int wm = (wid & 1) * 64, wn = (wid >> 1) * 32;
    #pragma unroll
    for (int mi = 0; mi < 4; ++mi)
        #pragma unroll
        for (int ni = 0; ni < 4; ++ni)
            #pragma unroll
            for (int h = 0; h < 2; ++h) {
                const size_t m = m0 + wm + mi * 16 + (lane >> 2) + h * 8;
                const int n = n0 + wn + ni * 8 + (lane & 3) * 2;
                float2 A;
                A.x = acc[mi][ni][h * 2];
                A.y = acc[mi][ni][h * 2 + 1];
                const float* xp = x1 + ((size_t)b * L + m) * HDIM + n;
                float2 xv = *(const float2*)xp;
                float* op = out + ((size_t)b * L + m) * OUTW + n;
                *(float2*)(op)            = xv;
                *(float2*)(op + HDIM)     = A;
                *(float2*)(op + 2 * HDIM) = make_float2(xv.x * A.x, xv.y * A.y);
                *(float2*)(op + 3 * HDIM) = make_float2(xv.x - A.x, xv.y - A.y);
            }
}

// ---------------------------------------------------------------------------
extern "C" void kernel_launch(void* const* d_in, const int* in_sizes, int n_in,
                              void* d_out, int out_size)
{
    const float* x1 = (const float*)d_in[0];
    const float* x2 = (const float*)d_in[1];
    // d_in[2] = x1_mask (unused by reference)
    const int* x2_mask = (const int*)d_in[3];
    const float* W    = (const float*)d_in[4];
    const float* bias = (const float*)d_in[5];
    float* out = (float*)d_out;

    cudaFuncSetAttribute(gemm_proj_xy, cudaFuncAttributeMaxDynamicSharedMemorySize, SMEMB);
    cudaFuncSetAttribute(gemm_scores,  cudaFuncAttributeMaxDynamicSharedMemorySize, SMEMB2);

    index_kernel<<<BSZ, 256>>>(x2_mask);
    split_kernel<<<(N4X + N4W + 255) / 256, 256>>>(x1, W);
    prep_x2<<<dim3(HDIM / 32, L / 32, BSZ), 256>>>(x2);

    gemm_proj_xy<<<dim3(HDIM / 128, 256), 256, SMEMB>>>(bias);
    gemm_scores<<<dim3(L / 128, L / 128, BSZ), 256, SMEMB2>>>();
    softmax_kernel<<<BSZ * L, 256>>>();
    gemm_att<<<dim3(HDIM / 128, L / 128, BSZ), 256>>>(x1, out);
}

// round 16
// speedup vs baseline: 1.4151x; 1.4151x over previous
#include <cuda_runtime.h>
#include <cuda_bf16.h>
#include <cuda_fp16.h>
#include <cstdint>

#define BSZ 16
#define L 1024
#define HDIM 768
#define OUTW (4*HDIM)

typedef __nv_bfloat16 bf16;

// ---------------- scratch (device globals; allocation-free rule) ------------
__device__ __align__(256) bf16 g_x1h[(size_t)BSZ*L*HDIM];
__device__ __align__(256) bf16 g_x1l[(size_t)BSZ*L*HDIM];
__device__ __align__(256) bf16 g_x2h[(size_t)BSZ*L*HDIM];   // gathered x2 rows hi (bf16)
__device__ __align__(256) bf16 g_x2l[(size_t)BSZ*L*HDIM];   // gathered x2 rows lo (bf16)
__device__ __align__(256) bf16 g_Wh [(size_t)HDIM*HDIM];
__device__ __align__(256) bf16 g_Wl [(size_t)HDIM*HDIM];
__device__ __align__(256) __half g_xph[(size_t)BSZ*L*HDIM]; // xproj hi (fp16)
__device__ __align__(256) __half g_xpl[(size_t)BSZ*L*HDIM]; // xproj lo (fp16)
__device__ __align__(256) __half g_yph[(size_t)BSZ*L*HDIM]; // yproj hi only (fp16)
__device__ __align__(256) __half g_x2Th[(size_t)BSZ*HDIM*L]; // gathered transpose (fp16)
__device__ __align__(256) __half g_ah [(size_t)BSZ*L*L];     // alpha (compacted cols)
__device__ float g_scores[(size_t)BSZ*L*L];
__device__ int g_cnt[BSZ];
__device__ int g_idx[BSZ][L];

// ---------------- helpers ---------------------------------------------------
__device__ __forceinline__ uint32_t smem_u32(const void* p) {
    uint32_t a;
    asm("{ .reg .u64 t; cvta.to.shared.u64 t, %1; cvt.u32.u64 %0, t; }"
        : "=r"(a) : "l"(p));
    return a;
}
__device__ __forceinline__ void cp16(uint32_t dst, const void* src) {
    asm volatile("cp.async.cg.shared.global [%0], [%1], 16;"
                 :: "r"(dst), "l"(src) : "memory");
}
__device__ __forceinline__ void ldmx4(uint32_t (&r)[4], uint32_t addr) {
    asm volatile("ldmatrix.sync.aligned.m8n8.x4.shared.b16 {%0,%1,%2,%3}, [%4];"
                 : "=r"(r[0]), "=r"(r[1]), "=r"(r[2]), "=r"(r[3]) : "r"(addr));
}
__device__ __forceinline__ void mma16816(float (&c)[4], const uint32_t (&a)[4],
                                         uint32_t b0, uint32_t b1) {
    asm volatile(
        "mma.sync.aligned.m16n8k16.row.col.f32.bf16.bf16.f32 "
        "{%0,%1,%2,%3}, {%4,%5,%6,%7}, {%8,%9}, {%0,%1,%2,%3};"
        : "+f"(c[0]), "+f"(c[1]), "+f"(c[2]), "+f"(c[3])
        : "r"(a[0]), "r"(a[1]), "r"(a[2]), "r"(a[3]), "r"(b0), "r"(b1));
}
__device__ __forceinline__ void mma16816_f16(float (&c)[4], const uint32_t (&a)[4],
                                             uint32_t b0, uint32_t b1) {
    asm volatile(
        "mma.sync.aligned.m16n8k16.row.col.f32.f16.f16.f32 "
        "{%0,%1,%2,%3}, {%4,%5,%6,%7}, {%8,%9}, {%0,%1,%2,%3};"
        : "+f"(c[0]), "+f"(c[1]), "+f"(c[2]), "+f"(c[3])
        : "r"(a[0]), "r"(a[1]), "r"(a[2]), "r"(a[3]), "r"(b0), "r"(b1));
}
__device__ __forceinline__ uint32_t pack_bf(bf16 a, bf16 b) {
    uint16_t ua = *(uint16_t*)&a, ub = *(uint16_t*)&b;
    return (uint32_t)ua | ((uint32_t)ub << 16);
}
__device__ __forceinline__ uint32_t pack_h(__half a, __half b) {
    uint16_t ua = *(uint16_t*)&a, ub = *(uint16_t*)&b;
    return (uint32_t)ua | ((uint32_t)ub << 16);
}
__device__ __forceinline__ void split1(float f, bf16& h, bf16& l) {
    h = __float2bfloat16(f);
    l = __float2bfloat16(f - __bfloat162float(h));
}
__device__ __forceinline__ void split1h(float f, __half& h, __half& l) {
    h = __float2half(f);
    l = __float2half(f - __half2float(h));
}

#define ROWB 80
#define TILEB (128 * ROWB)
#define STAGEB (4 * TILEB)
#define SMEMB (2 * STAGEB)          // 3-pass bf16: 81920
#define STAGEB2 (3 * TILEB)
#define SMEMB2 (2 * STAGEB2)        // 2-pass fp16: 61440
#define STAGEB1 (2 * TILEB)
#define SMEMB1 (2 * STAGEB1)        // 1-pass fp16: 40960 (static)

// ---------------------------------------------------------------------------
// 3-pass split-bf16 mainloop: acc += Ah.Bh^T + Ah.Bl^T + Al.Bh^T
// ---------------------------------------------------------------------------
__device__ __forceinline__ void gemm_core(
    const bf16* __restrict__ Ah, const bf16* __restrict__ Al, int lda,
    const bf16* __restrict__ Bh, const bf16* __restrict__ Bl, int ldb,
    int K, char* smem, float (&acc)[4][4][4])
{
    const int tid  = threadIdx.x;
    const int lane = tid & 31;
    const int wid  = tid >> 5;
    const int wm   = (wid & 1) * 64;
    const int wn   = (wid >> 1) * 32;
    const uint32_t sbase = smem_u32(smem);
    const int nk = K >> 5;

    const int ra = tid >> 2, ca = tid & 3;
    const int rb = ra + 64;

    for (int i = -1; i < nk; ++i) {
        if (i + 1 < nk) {
            const int kt = (i + 1) << 5;
            const uint32_t st = sbase + ((i + 1) & 1) * STAGEB;
            const uint32_t o0 = ra * ROWB + ca * 16;
            const uint32_t o1 = rb * ROWB + ca * 16;
            cp16(st + o0,             Ah + (size_t)ra * lda + kt + ca * 8);
            cp16(st + o1,             Ah + (size_t)rb * lda + kt + ca * 8);
            cp16(st + TILEB + o0,     Al + (size_t)ra * lda + kt + ca * 8);
            cp16(st + TILEB + o1,     Al + (size_t)rb * lda + kt + ca * 8);
            cp16(st + 2*TILEB + o0,   Bh + (size_t)ra * ldb + kt + ca * 8);
            cp16(st + 2*TILEB + o1,   Bh + (size_t)rb * ldb + kt + ca * 8);
            cp16(st + 3*TILEB + o0,   Bl + (size_t)ra * ldb + kt + ca * 8);
            cp16(st + 3*TILEB + o1,   Bl + (size_t)rb * ldb + kt + ca * 8);
            asm volatile("cp.async.commit_group;" ::: "memory");
        }
        if (i < 0) continue;
        if (i + 1 < nk)
            asm volatile("cp.async.wait_group 1;" ::: "memory");
        else
            asm volatile("cp.async.wait_group 0;" ::: "memory");
        __syncthreads();

        const uint32_t sAh = sbase + (i & 1) * STAGEB;
        const uint32_t sAl = sAh + TILEB;
        const uint32_t sBh = sAh + 2 * TILEB;
        const uint32_t sBl = sAh + 3 * TILEB;
        #pragma unroll
        for (int kh = 0; kh < 2; ++kh) {
            const uint32_t coff = (uint32_t)(kh * 2 + (lane >> 4)) * 16;
            const uint32_t brow = (uint32_t)(wn + (lane & 15)) * ROWB + coff;
            uint32_t bh0[4], bh1[4], bl0[4], bl1[4];
            ldmx4(bh0, sBh + brow);
            ldmx4(bh1, sBh + brow + 16u * ROWB);
            ldmx4(bl0, sBl + brow);
            ldmx4(bl1, sBl + brow + 16u * ROWB);
            #pragma unroll
            for (int mi = 0; mi < 4; ++mi) {
                const uint32_t arow = (uint32_t)(wm + mi * 16 + (lane & 15)) * ROWB + coff;
                uint32_t ah[4], al[4];
                ldmx4(ah, sAh + arow);
                ldmx4(al, sAl + arow);
                mma16816(acc[mi][0], ah, bh0[0], bh0[2]);
                mma16816(acc[mi][1], ah, bh0[1], bh0[3]);
                mma16816(acc[mi][2], ah, bh1[0], bh1[2]);
                mma16816(acc[mi][3], ah, bh1[1], bh1[3]);
                mma16816(acc[mi][0], ah, bl0[0], bl0[2]);
                mma16816(acc[mi][1], ah, bl0[1], bl0[3]);
                mma16816(acc[mi][2], ah, bl1[0], bl1[2]);
                mma16816(acc[mi][3], ah, bl1[1], bl1[3]);
                mma16816(acc[mi][0], al, bh0[0], bh0[2]);
                mma16816(acc[mi][1], al, bh0[1], bh0[3]);
                mma16816(acc[mi][2], al, bh1[0], bh1[2]);
                mma16816(acc[mi][3], al, bh1[1], bh1[3]);
            }
        }
        __syncthreads();
    }
}

// ---------------------------------------------------------------------------
// 2-pass fp16 mainloop: acc += (Ah + Al).Bh^T
// ---------------------------------------------------------------------------
__device__ __forceinline__ void gemm_core_2p(
    const __half* __restrict__ Ah, const __half* __restrict__ Al, int lda,
    const __half* __restrict__ Bh, int ldb,
    int K, char* smem, float (&acc)[4][4][4])
{
    const int tid  = threadIdx.x;
    const int lane = tid & 31;
    const int wid  = tid >> 5;
    const int wm   = (wid & 1) * 64;
    const int wn   = (wid >> 1) * 32;
    const uint32_t sbase = smem_u32(smem);
    const int nk = K >> 5;

    const int ra = tid >> 2, ca = tid & 3;
    const int rb = ra + 64;

    for (int i = -1; i < nk; ++i) {
        if (i + 1 < nk) {
            const int kt = (i + 1) << 5;
            const uint32_t st = sbase + ((i + 1) & 1) * STAGEB2;
            const uint32_t o0 = ra * ROWB + ca * 16;
            const uint32_t o1 = rb * ROWB + ca * 16;
            cp16(st + o0,           Ah + (size_t)ra * lda + kt + ca * 8);
            cp16(st + o1,           Ah + (size_t)rb * lda + kt + ca * 8);
            cp16(st + TILEB + o0,   Al + (size_t)ra * lda + kt + ca * 8);
            cp16(st + TILEB + o1,   Al + (size_t)rb * lda + kt + ca * 8);
            cp16(st + 2*TILEB + o0, Bh + (size_t)ra * ldb + kt + ca * 8);
            cp16(st + 2*TILEB + o1, Bh + (size_t)rb * ldb + kt + ca * 8);
            asm volatile("cp.async.commit_group;" ::: "memory");
        }
        if (i < 0) continue;
        if (i + 1 < nk)
            asm volatile("cp.async.wait_group 1;" ::: "memory");
        else
            asm volatile("cp.async.wait_group 0;" ::: "memory");
        __syncthreads();

        const uint32_t sAh = sbase + (i & 1) * STAGEB2;
        const uint32_t sAl = sAh + TILEB;
        const uint32_t sBh = sAh + 2 * TILEB;
        #pragma unroll
        for (int kh = 0; kh < 2; ++kh) {
            const uint32_t coff = (uint32_t)(kh * 2 + (lane >> 4)) * 16;
            const uint32_t brow = (uint32_t)(wn + (lane & 15)) * ROWB + coff;
            uint32_t bh0[4], bh1[4];
            ldmx4(bh0, sBh + brow);
            ldmx4(bh1, sBh + brow + 16u * ROWB);
            #pragma unroll
            for (int mi = 0; mi < 4; ++mi) {
                const uint32_t arow = (uint32_t)(wm + mi * 16 + (lane & 15)) * ROWB + coff;
                uint32_t ah[4], al[4];
                ldmx4(ah, sAh + arow);
                ldmx4(al, sAl + arow);
                mma16816_f16(acc[mi][0], ah, bh0[0], bh0[2]);
                mma16816_f16(acc[mi][1], ah, bh0[1], bh0[3]);
                mma16816_f16(acc[mi][2], ah, bh1[0], bh1[2]);
                mma16816_f16(acc[mi][3], ah, bh1[1], bh1[3]);
                mma16816_f16(acc[mi][0], al, bh0[0], bh0[2]);
                mma16816_f16(acc[mi][1], al, bh0[1], bh0[3]);
                mma16816_f16(acc[mi][2], al, bh1[0], bh1[2]);
                mma16816_f16(acc[mi][3], al, bh1[1], bh1[3]);
            }
        }
        __syncthreads();
    }
}

// ---------------------------------------------------------------------------
// 1-pass fp16 mainloop: acc += A.B^T
// ---------------------------------------------------------------------------
__device__ __forceinline__ void gemm_core_1p(
    const __half* __restrict__ A, int lda,
    const __half* __restrict__ B, int ldb,
    int K, char* smem, float (&acc)[4][4][4])
{
    const int tid  = threadIdx.x;
    const int lane = tid & 31;
    const int wid  = tid >> 5;
    const int wm   = (wid & 1) * 64;
    const int wn   = (wid >> 1) * 32;
    const uint32_t sbase = smem_u32(smem);
    const int nk = K >> 5;

    const int ra = tid >> 2, ca = tid & 3;
    const int rb = ra + 64;

    for (int i = -1; i < nk; ++i) {
        if (i + 1 < nk) {
            const int kt = (i + 1) << 5;
            const uint32_t st = sbase + ((i + 1) & 1) * STAGEB1;
            const uint32_t o0 = ra * ROWB + ca * 16;
            const uint32_t o1 = rb * ROWB + ca * 16;
            cp16(st + o0,         A + (size_t)ra * lda + kt + ca * 8);
            cp16(st + o1,         A + (size_t)rb * lda + kt + ca * 8);
            cp16(st + TILEB + o0, B + (size_t)ra * ldb + kt + ca * 8);
            cp16(st + TILEB + o1, B + (size_t)rb * ldb + kt + ca * 8);
            asm volatile("cp.async.commit_group;" ::: "memory");
        }
        if (i < 0) continue;
        if (i + 1 < nk)
            asm volatile("cp.async.wait_group 1;" ::: "memory");
        else
            asm volatile("cp.async.wait_group 0;" ::: "memory");
        __syncthreads();

        const uint32_t sA = sbase + (i & 1) * STAGEB1;
        const uint32_t sB = sA + TILEB;
        #pragma unroll
        for (int kh = 0; kh < 2; ++kh) {
            const uint32_t coff = (uint32_t)(kh * 2 + (lane >> 4)) * 16;
            const uint32_t brow = (uint32_t)(wn + (lane & 15)) * ROWB + coff;
            uint32_t bb0[4], bb1[4];
            ldmx4(bb0, sB + brow);
            ldmx4(bb1, sB + brow + 16u * ROWB);
            #pragma unroll
            for (int mi = 0; mi < 4; ++mi) {
                uint32_t aa[4];
                ldmx4(aa, sA + (uint32_t)(wm + mi * 16 + (lane & 15)) * ROWB + coff);
                mma16816_f16(acc[mi][0], aa, bb0[0], bb0[2]);
                mma16816_f16(acc[mi][1], aa, bb0[1], bb0[3]);
                mma16816_f16(acc[mi][2], aa, bb1[0], bb1[2]);
                mma16816_f16(acc[mi][3], aa, bb1[1], bb1[3]);
            }
        }
        __syncthreads();
    }
}

// ---------------------------------------------------------------------------
// Index build: per-batch compacted list of unmasked columns (block scan)
// ---------------------------------------------------------------------------
__global__ __launch_bounds__(256) void index_kernel(const int* __restrict__ x2_mask)
{
    const int b = blockIdx.x, tid = threadIdx.x;
    __shared__ int wsum[8];
    const int* m = x2_mask + (size_t)b * L;
    const int base = tid * 4;
    int keep[4], cnt = 0;
    #pragma unroll
    for (int j = 0; j < 4; ++j) { keep[j] = (m[base + j] == 0); cnt += keep[j]; }
    const int lane = tid & 31, w = tid >> 5;
    int v = cnt;
    #pragma unroll
    for (int o = 1; o < 32; o <<= 1) {
        int t = __shfl_up_sync(0xffffffffu, v, o);
        if (lane >= o) v += t;
    }
    if (lane == 31) wsum[w] = v;
    __syncthreads();
    int woff = 0;
    for (int i = 0; i < w; ++i) woff += wsum[i];
    int pos = woff + v - cnt;   // exclusive prefix
    #pragma unroll
    for (int j = 0; j < 4; ++j)
        if (keep[j]) g_idx[b][pos++] = base + j;
    if (tid == 255) g_cnt[b] = woff + v;
}

// ---------------------------------------------------------------------------
// Merged split (x1 then W), one launch
// ---------------------------------------------------------------------------
#define N4X (BSZ*L*HDIM/4)
#define N4W (HDIM*HDIM/4)
__global__ __launch_bounds__(256) void split_kernel(const float* __restrict__ x1,
                                                    const float* __restrict__ W)
{
    int i = blockIdx.x * 256 + threadIdx.x;
    const float* in;
    bf16 *hi, *lo;
    int j;
    if (i < N4X)      { in = x1; hi = g_x1h; lo = g_x1l; j = i; }
    else if (i < N4X + N4W) { in = W; hi = g_Wh; lo = g_Wl; j = i - N4X; }
    else return;
    float4 v = ((const float4*)in)[j];
    bf16 h0, h1, h2, h3, l0, l1, l2, l3;
    split1(v.x, h0, l0); split1(v.y, h1, l1);
    split1(v.z, h2, l2); split1(v.w, h3, l3);
    ((uint2*)hi)[j] = make_uint2(pack_bf(h0, h1), pack_bf(h2, h3));
    ((uint2*)lo)[j] = make_uint2(pack_bf(l0, l1), pack_bf(l2, l3));
}

// ---------------------------------------------------------------------------
// prep_x2: one x2 read -> compacted rows bf16 hi/lo + fp16 transpose
// ---------------------------------------------------------------------------
__global__ __launch_bounds__(256) void prep_x2(const float* __restrict__ x2)
{
    __shared__ float t[32][33];
    const int b = blockIdx.z;
    const int c = g_cnt[b];
    const int cpad = (c + 127) & ~127;
    const int h0 = blockIdx.x * 32, l0 = blockIdx.y * 32;
    if (l0 >= cpad) return;
    const int tx = threadIdx.x & 31, ty = threadIdx.x >> 5;
    #pragma unroll
    for (int j = 0; j < 4; ++j) {
        const int li = ty + j * 8;
        const int lg = l0 + li;
        float v = 0.f;
        if (lg < c) v = x2[((size_t)b * L + g_idx[b][lg]) * HDIM + h0 + tx];
        t[li][tx] = v;
        bf16 h, l; split1(v, h, l);
        const size_t o = ((size_t)b * L + lg) * HDIM + h0 + tx;
        g_x2h[o] = h;
        g_x2l[o] = l;
    }
    __syncthreads();
    #pragma unroll
    for (int j = 0; j < 4; ++j) {
        const int r = ty + j * 8;   // h-local
        g_x2Th[((size_t)b * HDIM + h0 + r) * L + l0 + tx] = __float2half(t[tx][r]);
    }
}

// ---------------------------------------------------------------------------
// GEMM 1a: xproj = relu(x1 @ W^T + b) -> fp16 hi/lo.  grid (6, 128)
// ---------------------------------------------------------------------------
__global__ __launch_bounds__(256, 2) void gemm_proj_x(const float* __restrict__ bias)
{
    extern __shared__ __align__(128) char gsm[];
    float acc[4][4][4] = {};

    const size_t m0 = (size_t)blockIdx.y * 128;
    const int n0 = blockIdx.x * 128;

    gemm_core(g_x1h + m0 * HDIM, g_x1l + m0 * HDIM, HDIM,
              g_Wh + (size_t)n0 * HDIM, g_Wl + (size_t)n0 * HDIM, HDIM,
              HDIM, gsm, acc);

    const int tid = threadIdx.x, lane = tid & 31, wid = tid >> 5;
    const int wm = (wid & 1) * 64, wn = (wid >> 1) * 32;
    #pragma unroll
    for (int mi = 0; mi < 4; ++mi)
        #pragma unroll
        for (int ni = 0; ni < 4; ++ni)
            #pragma unroll
            for (int h = 0; h < 2; ++h) {
                const size_t m = m0 + wm + mi * 16 + (lane >> 2) + h * 8;
                const int n = n0 + wn + ni * 8 + (lane & 3) * 2;
                float f0 = fmaxf(acc[mi][ni][h * 2]     + bias[n],     0.f);
                float f1 = fmaxf(acc[mi][ni][h * 2 + 1] + bias[n + 1], 0.f);
                __half h0, l0, h1, l1;
                split1h(f0, h0, l0); split1h(f1, h1, l1);
                *(uint32_t*)(g_xph + m * HDIM + n) = pack_h(h0, h1);
                *(uint32_t*)(g_xpl + m * HDIM + n) = pack_h(l0, l1);
            }
}

// ---------------------------------------------------------------------------
// GEMM 1b: yproj over compacted x2 rows -> fp16 hi only. grid (6, 8, 16)
// ---------------------------------------------------------------------------
__global__ __launch_bounds__(256, 2) void gemm_proj_y(const float* __restrict__ bias)
{
    extern __shared__ __align__(128) char gsm[];
    const int b = blockIdx.z;
    const int cpad = (g_cnt[b] + 127) & ~127;
    const size_t m0 = (size_t)blockIdx.y * 128;
    if ((int)m0 >= cpad) return;

    float acc[4][4][4] = {};
    const int n0 = blockIdx.x * 128;
    const size_t boff = (size_t)b * L * HDIM;

    gemm_core(g_x2h + boff + m0 * HDIM, g_x2l + boff + m0 * HDIM, HDIM,
              g_Wh + (size_t)n0 * HDIM, g_Wl + (size_t)n0 * HDIM, HDIM,
              HDIM, gsm, acc);

    const int tid = threadIdx.x, lane = tid & 31, wid = tid >> 5;
    const int wm = (wid & 1) * 64, wn = (wid >> 1) * 32;
    #pragma unroll
    for (int mi = 0; mi < 4; ++mi)
        #pragma unroll
        for (int ni = 0; ni < 4; ++ni)
            #pragma unroll
            for (int h = 0; h < 2; ++h) {
                const size_t m = m0 + wm + mi * 16 + (lane >> 2) + h * 8;
                const int n = n0 + wn + ni * 8 + (lane & 3) * 2;
                float f0 = fmaxf(acc[mi][ni][h * 2]     + bias[n],     0.f);
                float f1 = fmaxf(acc[mi][ni][h * 2 + 1] + bias[n + 1], 0.f);
                *(uint32_t*)(g_yph + boff + m * HDIM + n) =
                    pack_h(__float2half(f0), __float2half(f1));
            }
}

// ---------------------------------------------------------------------------
// GEMM 2: scores = (xh+xl) . yh^T (2-pass fp16), -inf beyond count. grid (8,8,16)
// ---------------------------------------------------------------------------
__global__ __launch_bounds__(256, 2) void gemm_scores()
{
    extern __shared__ __align__(128) char gsm[];
    const int b = blockIdx.z;
    const int c = g_cnt[b];
    const int cpad = (c + 127) & ~127;
    const int n0 = blockIdx.x * 128;
    if (n0 >= cpad) return;

    float acc[4][4][4] = {};
    const size_t m0 = (size_t)blockIdx.y * 128;
    const size_t boff = (size_t)b * L * HDIM;

    gemm_core_2p(g_xph + boff + m0 * HDIM, g_xpl + boff + m0 * HDIM, HDIM,
                 g_yph + boff + (size_t)n0 * HDIM, HDIM,
                 HDIM, gsm, acc);

    const int tid = threadIdx.x, lane = tid & 31, wid = tid >> 5;
    const int wm = (wid & 1) * 64, wn = (wid >> 1) * 32;
    const float NEGINF = __int_as_float(0xff800000u);
    #pragma unroll
    for (int mi = 0; mi < 4; ++mi)
        #pragma unroll
        for (int ni = 0; ni < 4; ++ni)
            #pragma unroll
            for (int h = 0; h < 2; ++h) {
                const size_t m = m0 + wm + mi * 16 + (lane >> 2) + h * 8;
                const int n = n0 + wn + ni * 8 + (lane & 3) * 2;
                float2 o;
                o.x = (n     >= c) ? NEGINF : acc[mi][ni][h * 2];
                o.y = (n + 1 >= c) ? NEGINF : acc[mi][ni][h * 2 + 1];
                *(float2*)(g_scores + ((size_t)b * L + m) * L + n) = o;
            }
}

// ---------------------------------------------------------------------------
// Softmax over compacted cols; fp16 alpha out. grid(16384), 256 threads.
// ---------------------------------------------------------------------------
__global__ __launch_bounds__(256) void softmax_kernel()
{
    const int tid = threadIdx.x;
    const size_t row = blockIdx.x;
    const int b = (int)(row >> 10);
    const int cpad = (g_cnt[b] + 127) & ~127;
    const int col = tid * 4;
    const float NEGINF = __int_as_float(0xff800000u);

    float4 v = make_float4(NEGINF, NEGINF, NEGINF, NEGINF);
    if (col < cpad)
        v = *(((const float4*)g_scores) + row * (L / 4) + tid);

    __shared__ float smax[8];
    __shared__ float ssum[8];

    float m = fmaxf(fmaxf(v.x, v.y), fmaxf(v.z, v.w));
    #pragma unroll
    for (int o = 16; o > 0; o >>= 1)
        m = fmaxf(m, __shfl_xor_sync(0xffffffffu, m, o));
    if ((tid & 31) == 0) smax[tid >> 5] = m;
    __syncthreads();
    m = smax[0];
    #pragma unroll
    for (int w = 1; w < 8; ++w) m = fmaxf(m, smax[w]);

    float4 e;
    e.x = expf(v.x - m); e.y = expf(v.y - m);
    e.z = expf(v.z - m); e.w = expf(v.w - m);
    float s = (e.x + e.y) + (e.z + e.w);
    #pragma unroll
    for (int o = 16; o > 0; o >>= 1)
        s += __shfl_xor_sync(0xffffffffu, s, o);
    if ((tid & 31) == 0) ssum[tid >> 5] = s;
    __syncthreads();
    s = 0.f;
    #pragma unroll
    for (int w = 0; w < 8; ++w) s += ssum[w];

    const float inv = 1.0f / s;
    if (col < cpad) {
        e.x *= inv; e.y *= inv; e.z *= inv; e.w *= inv;
        *(uint2*)(g_ah + row * L + col) = make_uint2(
            pack_h(__float2half(e.x), __float2half(e.y)),
            pack_h(__float2half(e.z), __float2half(e.w)));
    }
}

// ---------------------------------------------------------------------------
// GEMM 3: att = alpha @ x2 over compacted K + concat epilogue. grid (6, 8, 16)
// ---------------------------------------------------------------------------
__global__ __launch_bounds__(256, 2) void gemm_att(const float* __restrict__ x1,
                                                   float* __restrict__ out)
{
    __shared__ __align__(128) char gsm[SMEMB1];
    float acc[4][4][4] = {};

    const int b = blockIdx.z;
    const int cpad = (g_cnt[b] + 127) & ~127;
    const size_t m0 = (size_t)blockIdx.y * 128;
    const int n0 = blockIdx.x * 128;

    gemm_core_1p(g_ah + ((size_t)b * L + m0) * L, L,
                 g_x2Th + ((size_t)b * HDIM + n0) * L, L,
                 cpad, gsm, acc);

    const int tid = threadIdx.x, lane = tid & 31, wid = tid >> 5;
    const int wm = (wid & 1) * 64, wn = (wid >> 1) * 32;
    #pragma unroll
    for (int mi = 0; mi < 4; ++mi)
        #pragma unroll
        for (int ni = 0; ni < 4; ++ni)
            #pragma unroll
            for (int h = 0; h < 2; ++h) {
                const size_t m = m0 + wm + mi * 16 + (lane >> 2) + h * 8;
                const int n = n0 + wn + ni * 8 + (lane & 3) * 2;
                float2 A;
                A.x = acc[mi][ni][h * 2];
                A.y = acc[mi][ni][h * 2 + 1];
                const float* xp = x1 + ((size_t)b * L + m) * HDIM + n;
                float2 xv = *(const float2*)xp;
                float* op = out + ((size_t)b * L + m) * OUTW + n;
                *(float2*)(op)            = xv;
                *(float2*)(op + HDIM)     = A;
                *(float2*)(op + 2 * HDIM) = make_float2(xv.x * A.x, xv.y * A.y);
                *(float2*)(op + 3 * HDIM) = make_float2(xv.x - A.x, xv.y - A.y);
            }
}

// ---------------------------------------------------------------------------
extern "C" void kernel_launch(void* const* d_in, const int* in_sizes, int n_in,
                              void* d_out, int out_size)
{
    const float* x1 = (const float*)d_in[0];
    const float* x2 = (const float*)d_in[1];
    // d_in[2] = x1_mask (unused by reference)
    const int* x2_mask = (const int*)d_in[3];
    const float* W    = (const float*)d_in[4];
    const float* bias = (const float*)d_in[5];
    float* out = (float*)d_out;

    cudaFuncSetAttribute(gemm_proj_x, cudaFuncAttributeMaxDynamicSharedMemorySize, SMEMB);
    cudaFuncSetAttribute(gemm_proj_y, cudaFuncAttributeMaxDynamicSharedMemorySize, SMEMB);
    cudaFuncSetAttribute(gemm_scores, cudaFuncAttributeMaxDynamicSharedMemorySize, SMEMB2);

    index_kernel<<<BSZ, 256>>>(x2_mask);
    split_kernel<<<(N4X + N4W + 255) / 256, 256>>>(x1, W);
    prep_x2<<<dim3(HDIM / 32, L / 32, BSZ), 256>>>(x2);

    gemm_proj_x<<<dim3(HDIM / 128, (BSZ * L) / 128), 256, SMEMB>>>(bias);
    gemm_proj_y<<<dim3(HDIM / 128, L / 128, BSZ), 256, SMEMB>>>(bias);
    gemm_scores<<<dim3(L / 128, L / 128, BSZ), 256, SMEMB2>>>();
    softmax_kernel<<<BSZ * L, 256>>>();
    gemm_att<<<dim3(HDIM / 128, L / 128, BSZ), 256>>>(x1, out);
}